// round 1
// baseline (speedup 1.0000x reference)
#include <cuda_runtime.h>

#define N_NODES 32
#define D_EMB   96
#define N_EDGES 256
#define P_PAIRS 1024
#define M_TOT   262144   // P_PAIRS * N_EDGES

// ---- scratch (device globals: no allocations allowed) ----
__device__ float g_G[16 * M_TOT];       // conv features, layout [feature][sample]
__device__ float g_preds[M_TOT];        // masked MLP outputs, [p*256 + e]
__device__ float g_part[P_PAIRS * 32];  // per-p rbc partials

// =====================================================================
// Kernel 1: conv stack (thread per sample). 4x96 input -> 16 features.
// =====================================================================
__global__ void __launch_bounds__(256) conv_kernel(
    const float* __restrict__ emb, const int* __restrict__ edges,
    const float* __restrict__ w1, const float* __restrict__ b1,
    const float* __restrict__ w2, const float* __restrict__ b2,
    const float* __restrict__ w3, const float* __restrict__ b3)
{
    __shared__ float semb[N_NODES * D_EMB];
    __shared__ float sw1[48], sw2[48], sw3[48];
    __shared__ float sb1[4], sb2[4], sb3[4];
    int tid = threadIdx.x;
    for (int i = tid; i < N_NODES * D_EMB; i += 256) semb[i] = emb[i];
    if (tid < 48) { sw1[tid] = w1[tid]; sw2[tid] = w2[tid]; sw3[tid] = w3[tid]; }
    if (tid < 4)  { sb1[tid] = b1[tid]; sb2[tid] = b2[tid]; sb3[tid] = b3[tid]; }
    __syncthreads();

    int m = blockIdx.x * 256 + tid;
    int p = m >> 8, e = m & 255;
    int s = p >> 5, t = p & 31;
    int u = edges[2 * e], v = edges[2 * e + 1];
    const float* Xp[4] = { semb + s * D_EMB, semb + t * D_EMB,
                           semb + u * D_EMB, semb + v * D_EMB };

    // conv1 (k=3, stride 2, L 96->47) + relu + pool2 -> 23
    float p1[4][23];
    #pragma unroll
    for (int i = 0; i < 23; i++) {
        float xw[4][5];
        #pragma unroll
        for (int c = 0; c < 4; c++)
            #pragma unroll
            for (int q = 0; q < 5; q++) xw[c][q] = Xp[c][4 * i + q];
        #pragma unroll
        for (int o = 0; o < 4; o++) {
            float a0 = sb1[o], a1 = sb1[o];
            #pragma unroll
            for (int c = 0; c < 4; c++)
                #pragma unroll
                for (int k = 0; k < 3; k++) {
                    float wv = sw1[(o * 4 + c) * 3 + k];
                    a0 = fmaf(wv, xw[c][k],     a0);
                    a1 = fmaf(wv, xw[c][k + 2], a1);
                }
            p1[o][i] = fmaxf(fmaxf(a0, a1), 0.0f);  // relu(max) == max(relu)
        }
    }

    // conv2 (stride 1, 23->21) + relu + pool2 -> 10
    float p2[4][10];
    #pragma unroll
    for (int i = 0; i < 10; i++) {
        #pragma unroll
        for (int o = 0; o < 4; o++) {
            float a0 = sb2[o], a1 = sb2[o];
            #pragma unroll
            for (int c = 0; c < 4; c++)
                #pragma unroll
                for (int k = 0; k < 3; k++) {
                    float wv = sw2[(o * 4 + c) * 3 + k];
                    a0 = fmaf(wv, p1[c][2 * i + k],     a0);
                    a1 = fmaf(wv, p1[c][2 * i + 1 + k], a1);
                }
            p2[o][i] = fmaxf(fmaxf(a0, a1), 0.0f);
        }
    }

    // conv3 (10->8) + relu + pool2 -> 4; flatten [o*4 + pos]
    #pragma unroll
    for (int pos = 0; pos < 4; pos++) {
        #pragma unroll
        for (int o = 0; o < 4; o++) {
            float a0 = sb3[o], a1 = sb3[o];
            #pragma unroll
            for (int c = 0; c < 4; c++)
                #pragma unroll
                for (int k = 0; k < 3; k++) {
                    float wv = sw3[(o * 4 + c) * 3 + k];
                    a0 = fmaf(wv, p2[c][2 * pos + k],     a0);
                    a1 = fmaf(wv, p2[c][2 * pos + 1 + k], a1);
                }
            float g = fmaxf(fmaxf(a0, a1), 0.0f);
            g_G[(o * 4 + pos) * M_TOT + m] = g;   // coalesced per warp
        }
    }
}

// =====================================================================
// Kernel 2: fused FC chain. Block = 128-sample tile, 256 threads.
// smem: A3T (256x128 = 128KB) | A2T (128x128 = 64KB) | WS (16x128 = 8KB)
// Activations stored transposed [k][m] for conflict-free float4 LDS.
// =====================================================================
#define SMEM_A2T_OFF 32768
#define SMEM_WS_OFF  49152
#define SMEM_FLOATS  51200   // 204800 bytes

template<int K>
__device__ __forceinline__ void gemm_phase(
    const float* __restrict__ As,   // smem [K][128]
    const float* __restrict__ Wg,   // global, row-major [K][wstride]
    int wstride, int ncol0,
    const float* __restrict__ bias, // global bias (offset by ncol0)
    float* Out,                     // smem [n][128] (caller pre-offset)
    float* WS, int tid)
{
    const int tm = tid & 15, tn = tid >> 4;  // 16 x 16 threads, tile 8m x 8n
    float acc[8][8];
    #pragma unroll
    for (int i = 0; i < 8; i++)
        #pragma unroll
        for (int j = 0; j < 8; j++) acc[i][j] = 0.0f;

    for (int kt = 0; kt < K; kt += 16) {
        __syncthreads();  // protect WS reuse + As producer visibility
        for (int idx = tid; idx < 2048; idx += 256) {
            int kk = idx >> 7, nn = idx & 127;
            WS[idx] = Wg[(kt + kk) * wstride + ncol0 + nn];
        }
        __syncthreads();
        #pragma unroll 4
        for (int kk = 0; kk < 16; kk++) {
            const float4* ap = (const float4*)(As + (kt + kk) * 128 + tm * 8);
            float4 a0 = ap[0], a1 = ap[1];
            const float4* wp = (const float4*)(WS + kk * 128 + tn * 8);
            float4 w0 = wp[0], w1 = wp[1];
            float av[8] = {a0.x, a0.y, a0.z, a0.w, a1.x, a1.y, a1.z, a1.w};
            float wv[8] = {w0.x, w0.y, w0.z, w0.w, w1.x, w1.y, w1.z, w1.w};
            #pragma unroll
            for (int i = 0; i < 8; i++)
                #pragma unroll
                for (int j = 0; j < 8; j++)
                    acc[i][j] = fmaf(av[i], wv[j], acc[i][j]);
        }
    }
    __syncthreads();
    #pragma unroll
    for (int j = 0; j < 8; j++) {
        float bj = bias[ncol0 + tn * 8 + j];
        float4 o0, o1;
        o0.x = fmaxf(acc[0][j] + bj, 0.0f);
        o0.y = fmaxf(acc[1][j] + bj, 0.0f);
        o0.z = fmaxf(acc[2][j] + bj, 0.0f);
        o0.w = fmaxf(acc[3][j] + bj, 0.0f);
        o1.x = fmaxf(acc[4][j] + bj, 0.0f);
        o1.y = fmaxf(acc[5][j] + bj, 0.0f);
        o1.z = fmaxf(acc[6][j] + bj, 0.0f);
        o1.w = fmaxf(acc[7][j] + bj, 0.0f);
        float4* op = (float4*)(Out + (tn * 8 + j) * 128 + tm * 8);
        op[0] = o0; op[1] = o1;
    }
}

__global__ void __launch_bounds__(256) fc_kernel(
    const float* __restrict__ fc1w, const float* __restrict__ fc1b,
    const float* __restrict__ fc2w, const float* __restrict__ fc2b,
    const float* __restrict__ fc3w, const float* __restrict__ fc3b,
    const float* __restrict__ fc4w, const float* __restrict__ fc4b)
{
    extern __shared__ float sm[];
    float* A3T = sm;                  // also hosts GT [16][128] initially
    float* A2T = sm + SMEM_A2T_OFF;
    float* WS  = sm + SMEM_WS_OFF;
    int tid = threadIdx.x;
    int m0 = blockIdx.x * 128;

    // stage conv features GT[k][mm]
    for (int idx = tid; idx < 16 * 128; idx += 256) {
        int k = idx >> 7, mm = idx & 127;
        A3T[idx] = g_G[k * M_TOT + m0 + mm];
    }
    __syncthreads();

    gemm_phase<16 >(A3T, fc1w, 128, 0,   fc1b, A2T,             WS, tid); // fc1: GT->A2T
    gemm_phase<128>(A2T, fc2w, 256, 0,   fc2b, A3T,             WS, tid); // fc2 n[0,128)
    gemm_phase<128>(A2T, fc2w, 256, 128, fc2b, A3T + 128 * 128, WS, tid); // fc2 n[128,256)
    gemm_phase<256>(A3T, fc3w, 128, 0,   fc3b, A2T,             WS, tid); // fc3 -> A4T(=A2T)
    __syncthreads();

    // fc4: out[m] = sum_k A4T[k][m] * w4[k] + b4, split K over 2 halves
    int mm = tid & 127, half = tid >> 7;
    float ssum = 0.0f;
    #pragma unroll 8
    for (int k = half * 64; k < half * 64 + 64; k++)
        ssum = fmaf(A2T[k * 128 + mm], fc4w[k], ssum);
    WS[half * 128 + mm] = ssum;
    __syncthreads();
    if (tid < 128) {
        float r = WS[tid] + WS[128 + tid] + fc4b[0];
        int m = m0 + tid;
        int p = m >> 8;
        if ((p >> 5) == (p & 31)) r = 0.0f;   // mask s==t rows
        g_preds[m] = r;
    }
}

// =====================================================================
// Kernel 3: 3-step propagation, block per p. Deterministic (no atomics).
// =====================================================================
__global__ void __launch_bounds__(256) prop_kernel(const int* __restrict__ edges)
{
    __shared__ float xs[32];
    __shared__ float xn[8][32];
    __shared__ float acc[32];
    __shared__ float pr[256];
    __shared__ int   su[256], sv[256];
    int tid = threadIdx.x;
    int p = blockIdx.x;
    int s = p >> 5, t = p & 31;
    pr[tid] = g_preds[p * 256 + tid];
    su[tid] = edges[2 * tid];
    sv[tid] = edges[2 * tid + 1];
    if (tid < 32) { xs[tid] = (tid == s) ? 1.0f : 0.0f; acc[tid] = 0.0f; }
    __syncthreads();
    if (s != t) {
        int j = tid & 31, grp = tid >> 5;
        for (int step = 0; step < 3; step++) {
            float sum = 0.0f;
            #pragma unroll 4
            for (int q = 0; q < 32; q++) {
                int e = grp * 32 + q;
                sum += (sv[e] == j) ? xs[su[e]] * pr[e] : 0.0f;
            }
            xn[grp][j] = sum;
            __syncthreads();
            if (tid < 32) {
                float v = 0.0f;
                #pragma unroll
                for (int g2 = 0; g2 < 8; g2++) v += xn[g2][tid];
                xs[tid] = v;
                acc[tid] += v;
            }
            __syncthreads();
        }
    }
    if (tid < 32) g_part[p * 32 + tid] = acc[tid];
}

// =====================================================================
// Kernel 4: final reduction + normalize (single block, deterministic).
// =====================================================================
__global__ void __launch_bounds__(1024) reduce_kernel(float* __restrict__ out)
{
    __shared__ float red[32][32];
    __shared__ float rbc[32];
    __shared__ float tot;
    int tid = threadIdx.x;
    int j = tid & 31, chunk = tid >> 5;
    float sum = 0.0f;
    for (int q = 0; q < 32; q++)
        sum += g_part[(chunk * 32 + q) * 32 + j];
    red[chunk][j] = sum;
    __syncthreads();
    if (tid < 32) {
        float v = 0.0f;
        for (int c = 0; c < 32; c++) v += red[c][tid];
        rbc[tid] = v;
    }
    __syncthreads();
    if (tid == 0) {
        float tt = 0.0f;
        for (int k = 0; k < 32; k++) tt += rbc[k];
        tot = tt;
    }
    __syncthreads();
    if (tid < 32) out[tid] = rbc[tid] / tot;
}

// =====================================================================
extern "C" void kernel_launch(void* const* d_in, const int* in_sizes, int n_in,
                              void* d_out, int out_size)
{
    const float* emb   = (const float*)d_in[0];
    const int*   edges = (const int*)  d_in[1];
    const float* w1    = (const float*)d_in[2];
    const float* b1    = (const float*)d_in[3];
    const float* w2    = (const float*)d_in[4];
    const float* b2    = (const float*)d_in[5];
    const float* w3    = (const float*)d_in[6];
    const float* b3    = (const float*)d_in[7];
    const float* fc1w  = (const float*)d_in[8];
    const float* fc1b  = (const float*)d_in[9];
    const float* fc2w  = (const float*)d_in[10];
    const float* fc2b  = (const float*)d_in[11];
    const float* fc3w  = (const float*)d_in[12];
    const float* fc3b  = (const float*)d_in[13];
    const float* fc4w  = (const float*)d_in[14];
    const float* fc4b  = (const float*)d_in[15];

    conv_kernel<<<M_TOT / 256, 256>>>(emb, edges, w1, b1, w2, b2, w3, b3);

    size_t smem_bytes = SMEM_FLOATS * sizeof(float);  // 204800 B (opt-in)
    cudaFuncSetAttribute(fc_kernel, cudaFuncAttributeMaxDynamicSharedMemorySize,
                         (int)smem_bytes);
    fc_kernel<<<M_TOT / 128, 256, smem_bytes>>>(fc1w, fc1b, fc2w, fc2b,
                                                fc3w, fc3b, fc4w, fc4b);

    prop_kernel<<<P_PAIRS, 256>>>(edges);
    reduce_kernel<<<1, 1024>>>((float*)d_out);
}